// round 6
// baseline (speedup 1.0000x reference)
#include <cuda_runtime.h>
#include <cstdint>

#define V_NUM 80000
#define P_NUM 20
#define C_OUT 64
#define NY 640
#define NX 640
#define B_NUM 4

static constexpr float BN_EPS = 0.001f;
static constexpr size_t PLANE  = (size_t)NY * NX;                 // 409600
static constexpr size_t CANVAS = (size_t)B_NUM * C_OUT * PLANE;   // 104857600
static constexpr int    MAP_N  = B_NUM * NY * NX;                 // 1638400

__device__ __constant__ float kVX   = 100.0f / 640.0f;
__device__ __constant__ float kXOFF = 100.0f / 640.0f * 0.5f - 50.0f;

// Scratch. g_map / g_pix are zero-initialized at module load; the
// self-validation scheme (g_pix[g_map[pix]] == pix) makes per-call clearing
// unnecessary.
__device__ float g_feats[(size_t)V_NUM * C_OUT];   // 20.5 MB
__device__ int   g_map[MAP_N];                     // pixel -> voxel id
__device__ int   g_pix[V_NUM];                     // voxel id -> pixel

// ---------------------------------------------------------------------------
// Kernel 1: per-voxel features -> g_feats (coalesced), id <-> pixel links.
// One warp per voxel; lane handles channels {lane, lane+32}.
// Per-warp fold (coalesced W loads, all L1/L2 hits); inner loop uses
// pipelined float4 L1-hit loads.
// h = x*A + y*B + z*C + w*D + E_v
// ---------------------------------------------------------------------------
__global__ void __launch_bounds__(256)
compute_feats_kernel(const float* __restrict__ voxels,
                     const int*   __restrict__ num_points,
                     const int*   __restrict__ coors,
                     const float* __restrict__ W,
                     const float* __restrict__ gamma,
                     const float* __restrict__ beta,
                     const float* __restrict__ rmean,
                     const float* __restrict__ rvar)
{
    const int v = blockIdx.x * (blockDim.x >> 5) + (threadIdx.x >> 5);
    if (v >= V_NUM) return;
    const int lane = threadIdx.x & 31;

    const float4* __restrict__ vox =
        reinterpret_cast<const float4*>(voxels) + (size_t)v * P_NUM;

    int npv = num_points[v];
    npv = npv < 0 ? 0 : (npv > P_NUM ? P_NUM : npv);

    // mean over valid points via warp reduction
    float sx = 0.f, sy = 0.f, sz = 0.f;
    if (lane < npv) {
        float4 pt = vox[lane];
        sx = pt.x; sy = pt.y; sz = pt.z;
    }
    #pragma unroll
    for (int o = 16; o; o >>= 1) {
        sx += __shfl_xor_sync(0xffffffffu, sx, o);
        sy += __shfl_xor_sync(0xffffffffu, sy, o);
        sz += __shfl_xor_sync(0xffffffffu, sz, o);
    }
    const float inv_n = 1.0f / (float)(npv > 1 ? npv : 1);
    const float mx = sx * inv_n, my = sy * inv_n, mz = sz * inv_n;

    const int b  = coors[v * 4 + 0];
    const int yy = coors[v * 4 + 2];
    const int xx = coors[v * 4 + 3];
    const float cx = (float)xx * kVX + kXOFF;
    const float cy = (float)yy * kVX + kXOFF;

    // per-warp fold (channels c0=lane, c1=lane+32); coalesced loads
    const int c0 = lane, c1 = lane + 32;
    const float s0 = rsqrtf(rvar[c0] + BN_EPS) * gamma[c0];
    const float s1 = rsqrtf(rvar[c1] + BN_EPS) * gamma[c1];
    const float bb0 = beta[c0] - rmean[c0] * s0;
    const float bb1 = beta[c1] - rmean[c1] * s1;

    float sw0[9], sw1[9];
    #pragma unroll
    for (int i = 0; i < 9; i++) {
        sw0[i] = W[i * C_OUT + c0] * s0;
        sw1[i] = W[i * C_OUT + c1] * s1;
    }
    const float A0 = sw0[0] + sw0[4] + sw0[7];
    const float B0 = sw0[1] + sw0[5] + sw0[8];
    const float C0 = sw0[2] + sw0[6];
    const float D0 = sw0[3];
    const float A1 = sw1[0] + sw1[4] + sw1[7];
    const float B1 = sw1[1] + sw1[5] + sw1[8];
    const float C1 = sw1[2] + sw1[6];
    const float D1 = sw1[3];
    const float E0 = bb0 - (mx * sw0[4] + my * sw0[5] + mz * sw0[6]
                          + cx * sw0[7] + cy * sw0[8]);
    const float E1 = bb1 - (mx * sw1[4] + my * sw1[5] + mz * sw1[6]
                          + cx * sw1[7] + cy * sw1[8]);

    // masked (zero-feature) points contribute relu(BN bias) to the max
    float m0 = (npv < P_NUM) ? fmaxf(bb0, 0.0f) : -3.4e38f;
    float m1 = (npv < P_NUM) ? fmaxf(bb1, 0.0f) : -3.4e38f;

    for (int p = 0; p < npv; p++) {
        const float4 pt = vox[p];          // L1 hit (warp-broadcast)
        float h0 = fmaf(pt.x, A0, E0);
        float h1 = fmaf(pt.x, A1, E1);
        h0 = fmaf(pt.y, B0, h0);   h1 = fmaf(pt.y, B1, h1);
        h0 = fmaf(pt.z, C0, h0);   h1 = fmaf(pt.z, C1, h1);
        h0 = fmaf(pt.w, D0, h0);   h1 = fmaf(pt.w, D1, h1);
        m0 = fmaxf(m0, fmaxf(h0, 0.0f));
        m1 = fmaxf(m1, fmaxf(h1, 0.0f));
    }

    g_feats[(size_t)v * C_OUT + c0] = m0;
    g_feats[(size_t)v * C_OUT + c1] = m1;
    if (lane == 0) {
        const int pix = b * (NY * NX) + yy * NX + xx;
        g_map[pix] = v;
        g_pix[v]   = pix;
    }
}

// ---------------------------------------------------------------------------
// Kernel 2: coalesced render of canvas + occ, full-row tiles for DRAM page
// locality. Block = 512 threads, owns one full (b, y) x-row (640 pixels),
// all 64 channels -> 2560 B contiguous written per plane per block.
// Warp w handles channels {w, w+16, w+32, w+48}; each warp writes 5
// consecutive float4 quads per channel (ascending addresses).
// ---------------------------------------------------------------------------
__global__ void __launch_bounds__(512)
render_kernel(float* __restrict__ out)
{
    __shared__ int map_s[NX];

    const int y = blockIdx.x;
    const int b = blockIdx.y;
    const int t = threadIdx.x;
    const int lane = t & 31;
    const int w    = t >> 5;            // 0..15

    const int pix_base = b * (NY * NX) + y * NX;
    for (int i = t; i < NX; i += 512) {
        const int pix = pix_base + i;
        int v = g_map[pix];
        if (g_pix[v] != pix) v = -1;    // stale / zero-init -> invalid
        map_s[i] = v;
    }
    __syncthreads();

    const size_t row_base = (size_t)y * NX;

    #pragma unroll
    for (int q = 0; q < 5; q++) {
        const int xq = (lane + q * 32) * 4;      // 0..636
        const int v0 = map_s[xq + 0];
        const int v1 = map_s[xq + 1];
        const int v2 = map_s[xq + 2];
        const int v3 = map_s[xq + 3];

        #pragma unroll
        for (int k = 0; k < 4; k++) {
            const int c = w + k * 16;
            float4 val = make_float4(0.f, 0.f, 0.f, 0.f);
            if (v0 >= 0) val.x = g_feats[(size_t)v0 * C_OUT + c];
            if (v1 >= 0) val.y = g_feats[(size_t)v1 * C_OUT + c];
            if (v2 >= 0) val.z = g_feats[(size_t)v2 * C_OUT + c];
            if (v3 >= 0) val.w = g_feats[(size_t)v3 * C_OUT + c];
            float4* dst = reinterpret_cast<float4*>(
                out + ((size_t)(b * C_OUT + c)) * PLANE + row_base + xq);
            __stcs(dst, val);           // streaming: keep feats/map in L2
        }
    }

    // occupancy plane: threads 0..159 write the 640-pixel row as float4
    if (t < NX / 4) {
        const int xq = t * 4;
        float4 occ = make_float4(map_s[xq + 0] >= 0 ? 1.f : 0.f,
                                 map_s[xq + 1] >= 0 ? 1.f : 0.f,
                                 map_s[xq + 2] >= 0 ? 1.f : 0.f,
                                 map_s[xq + 3] >= 0 ? 1.f : 0.f);
        float4* dst = reinterpret_cast<float4*>(
            out + CANVAS + (size_t)b * PLANE + row_base + xq);
        __stcs(dst, occ);
    }
}

extern "C" void kernel_launch(void* const* d_in, const int* in_sizes, int n_in,
                              void* d_out, int out_size)
{
    const float* voxels     = (const float*)d_in[0];
    const int*   num_points = (const int*)  d_in[1];
    const int*   coors      = (const int*)  d_in[2];
    const float* W          = (const float*)d_in[3];
    const float* gamma      = (const float*)d_in[4];
    const float* beta       = (const float*)d_in[5];
    const float* rmean      = (const float*)d_in[6];
    const float* rvar       = (const float*)d_in[7];
    float* out = (float*)d_out;

    compute_feats_kernel<<<(V_NUM + 7) / 8, 256>>>(voxels, num_points, coors,
                                                   W, gamma, beta, rmean, rvar);

    dim3 grid(NY, B_NUM);
    render_kernel<<<grid, 512>>>(out);
}

// round 7
// speedup vs baseline: 1.0526x; 1.0526x over previous
#include <cuda_runtime.h>
#include <cstdint>

#define V_NUM 80000
#define P_NUM 20
#define C_OUT 64
#define NY 640
#define NX 640
#define B_NUM 4

static constexpr float BN_EPS = 0.001f;
static constexpr size_t PLANE  = (size_t)NY * NX;                 // 409600
static constexpr size_t CANVAS = (size_t)B_NUM * C_OUT * PLANE;   // 104857600
static constexpr int    MAP_N  = B_NUM * NY * NX;                 // 1638400

__device__ __constant__ float kVX   = 100.0f / 640.0f;
__device__ __constant__ float kXOFF = 100.0f / 640.0f * 0.5f - 50.0f;

// Scratch. g_map / g_pix are zero-initialized at module load; the
// self-validation scheme (g_pix[g_map[pix]] == pix) makes per-call clearing
// unnecessary.
__device__ float g_feats[(size_t)V_NUM * C_OUT];   // 20.5 MB
__device__ int   g_map[MAP_N];                     // pixel -> voxel id
__device__ int   g_pix[V_NUM];                     // voxel id -> pixel

// ---------------------------------------------------------------------------
// Kernel 1: per-voxel features -> g_feats (coalesced), id <-> pixel links.
// One warp per voxel; lane handles channels {lane, lane+32}.
// Per-warp fold (coalesced W loads, all L1/L2 hits); inner loop uses
// pipelined float4 L1-hit loads.  h = x*A + y*B + z*C + w*D + E_v
// (Measured ~15.5us in round 6.)
// ---------------------------------------------------------------------------
__global__ void __launch_bounds__(256)
compute_feats_kernel(const float* __restrict__ voxels,
                     const int*   __restrict__ num_points,
                     const int*   __restrict__ coors,
                     const float* __restrict__ W,
                     const float* __restrict__ gamma,
                     const float* __restrict__ beta,
                     const float* __restrict__ rmean,
                     const float* __restrict__ rvar)
{
    const int v = blockIdx.x * (blockDim.x >> 5) + (threadIdx.x >> 5);
    if (v >= V_NUM) return;
    const int lane = threadIdx.x & 31;

    const float4* __restrict__ vox =
        reinterpret_cast<const float4*>(voxels) + (size_t)v * P_NUM;

    int npv = num_points[v];
    npv = npv < 0 ? 0 : (npv > P_NUM ? P_NUM : npv);

    // mean over valid points via warp reduction
    float sx = 0.f, sy = 0.f, sz = 0.f;
    if (lane < npv) {
        float4 pt = vox[lane];
        sx = pt.x; sy = pt.y; sz = pt.z;
    }
    #pragma unroll
    for (int o = 16; o; o >>= 1) {
        sx += __shfl_xor_sync(0xffffffffu, sx, o);
        sy += __shfl_xor_sync(0xffffffffu, sy, o);
        sz += __shfl_xor_sync(0xffffffffu, sz, o);
    }
    const float inv_n = 1.0f / (float)(npv > 1 ? npv : 1);
    const float mx = sx * inv_n, my = sy * inv_n, mz = sz * inv_n;

    const int b  = coors[v * 4 + 0];
    const int yy = coors[v * 4 + 2];
    const int xx = coors[v * 4 + 3];
    const float cx = (float)xx * kVX + kXOFF;
    const float cy = (float)yy * kVX + kXOFF;

    // per-warp fold (channels c0=lane, c1=lane+32); coalesced loads
    const int c0 = lane, c1 = lane + 32;
    const float s0 = rsqrtf(rvar[c0] + BN_EPS) * gamma[c0];
    const float s1 = rsqrtf(rvar[c1] + BN_EPS) * gamma[c1];
    const float bb0 = beta[c0] - rmean[c0] * s0;
    const float bb1 = beta[c1] - rmean[c1] * s1;

    float sw0[9], sw1[9];
    #pragma unroll
    for (int i = 0; i < 9; i++) {
        sw0[i] = W[i * C_OUT + c0] * s0;
        sw1[i] = W[i * C_OUT + c1] * s1;
    }
    const float A0 = sw0[0] + sw0[4] + sw0[7];
    const float B0 = sw0[1] + sw0[5] + sw0[8];
    const float C0 = sw0[2] + sw0[6];
    const float D0 = sw0[3];
    const float A1 = sw1[0] + sw1[4] + sw1[7];
    const float B1 = sw1[1] + sw1[5] + sw1[8];
    const float C1 = sw1[2] + sw1[6];
    const float D1 = sw1[3];
    const float E0 = bb0 - (mx * sw0[4] + my * sw0[5] + mz * sw0[6]
                          + cx * sw0[7] + cy * sw0[8]);
    const float E1 = bb1 - (mx * sw1[4] + my * sw1[5] + mz * sw1[6]
                          + cx * sw1[7] + cy * sw1[8]);

    // masked (zero-feature) points contribute relu(BN bias) to the max
    float m0 = (npv < P_NUM) ? fmaxf(bb0, 0.0f) : -3.4e38f;
    float m1 = (npv < P_NUM) ? fmaxf(bb1, 0.0f) : -3.4e38f;

    for (int p = 0; p < npv; p++) {
        const float4 pt = vox[p];          // L1 hit (warp-broadcast)
        float h0 = fmaf(pt.x, A0, E0);
        float h1 = fmaf(pt.x, A1, E1);
        h0 = fmaf(pt.y, B0, h0);   h1 = fmaf(pt.y, B1, h1);
        h0 = fmaf(pt.z, C0, h0);   h1 = fmaf(pt.z, C1, h1);
        h0 = fmaf(pt.w, D0, h0);   h1 = fmaf(pt.w, D1, h1);
        m0 = fmaxf(m0, fmaxf(h0, 0.0f));
        m1 = fmaxf(m1, fmaxf(h1, 0.0f));
    }

    g_feats[(size_t)v * C_OUT + c0] = m0;
    g_feats[(size_t)v * C_OUT + c1] = m1;
    if (lane == 0) {
        const int pix = b * (NY * NX) + yy * NX + xx;
        g_map[pix] = v;
        g_pix[v]   = pix;
    }
}

// ---------------------------------------------------------------------------
// Kernel 2: coalesced render of canvas + occ (round-5 shape, measured 79.5us).
// Block = 256 threads, owns 128 pixels of one (b,y) row, all 64 channels.
// ---------------------------------------------------------------------------
__global__ void __launch_bounds__(256)
render_kernel(float* __restrict__ out)
{
    __shared__ int map_s[128];

    const int b  = blockIdx.z;
    const int y  = blockIdx.y;
    const int x0 = blockIdx.x * 128;
    const int t  = threadIdx.x;

    const int pix_base = b * (NY * NX) + y * NX + x0;
    if (t < 128) {
        const int pix = pix_base + t;
        int v = g_map[pix];
        if (g_pix[v] != pix) v = -1;   // stale / zero-init -> invalid
        map_s[t] = v;
    }
    __syncthreads();

    const int xq  = (t & 31) * 4;
    const int row = t >> 5;            // 0..7

    const int v0 = map_s[xq + 0];
    const int v1 = map_s[xq + 1];
    const int v2 = map_s[xq + 2];
    const int v3 = map_s[xq + 3];

    const size_t out_xbase = (size_t)y * NX + x0 + xq;

    #pragma unroll
    for (int k = 0; k < 8; k++) {
        const int c = row + k * 8;
        float4 val = make_float4(0.f, 0.f, 0.f, 0.f);
        if (v0 >= 0) val.x = g_feats[(size_t)v0 * C_OUT + c];
        if (v1 >= 0) val.y = g_feats[(size_t)v1 * C_OUT + c];
        if (v2 >= 0) val.z = g_feats[(size_t)v2 * C_OUT + c];
        if (v3 >= 0) val.w = g_feats[(size_t)v3 * C_OUT + c];
        float4* dst = reinterpret_cast<float4*>(
            out + ((size_t)(b * C_OUT + c)) * PLANE + out_xbase);
        __stcs(dst, val);              // streaming: keep feats/map in L2
    }

    if (t < 32) {
        float4 occ = make_float4(v0 >= 0 ? 1.f : 0.f,
                                 v1 >= 0 ? 1.f : 0.f,
                                 v2 >= 0 ? 1.f : 0.f,
                                 v3 >= 0 ? 1.f : 0.f);
        float4* dst = reinterpret_cast<float4*>(
            out + CANVAS + (size_t)b * PLANE + out_xbase);
        __stcs(dst, occ);
    }
}

extern "C" void kernel_launch(void* const* d_in, const int* in_sizes, int n_in,
                              void* d_out, int out_size)
{
    const float* voxels     = (const float*)d_in[0];
    const int*   num_points = (const int*)  d_in[1];
    const int*   coors      = (const int*)  d_in[2];
    const float* W          = (const float*)d_in[3];
    const float* gamma      = (const float*)d_in[4];
    const float* beta       = (const float*)d_in[5];
    const float* rmean      = (const float*)d_in[6];
    const float* rvar       = (const float*)d_in[7];
    float* out = (float*)d_out;

    compute_feats_kernel<<<(V_NUM + 7) / 8, 256>>>(voxels, num_points, coors,
                                                   W, gamma, beta, rmean, rvar);

    dim3 grid(NX / 128, NY, B_NUM);
    render_kernel<<<grid, 256>>>(out);
}

// round 8
// speedup vs baseline: 1.0627x; 1.0095x over previous
#include <cuda_runtime.h>
#include <cstdint>

#define V_NUM 80000
#define P_NUM 20
#define C_OUT 64
#define NY 640
#define NX 640
#define B_NUM 4

static constexpr float BN_EPS = 0.001f;
static constexpr size_t PLANE  = (size_t)NY * NX;                 // 409600
static constexpr size_t CANVAS = (size_t)B_NUM * C_OUT * PLANE;   // 104857600
static constexpr int    MAP_N  = B_NUM * NY * NX;                 // 1638400

__device__ __constant__ float kVX   = 100.0f / 640.0f;
__device__ __constant__ float kXOFF = 100.0f / 640.0f * 0.5f - 50.0f;

// Scratch. g_map / g_pix are zero-initialized at module load; the
// self-validation scheme (g_pix[g_map[pix]] == pix) makes per-call clearing
// unnecessary.
__device__ float g_feats[(size_t)V_NUM * C_OUT];   // 20.5 MB
__device__ int   g_map[MAP_N];                     // pixel -> voxel id
__device__ int   g_pix[V_NUM];                     // voxel id -> pixel

// ---- packed f32x2 helpers (Blackwell FFMA2 path) --------------------------
__device__ __forceinline__ unsigned long long pk2(float lo, float hi) {
    unsigned long long r;
    asm("mov.b64 %0, {%1, %2};" : "=l"(r) : "f"(lo), "f"(hi));
    return r;
}
__device__ __forceinline__ unsigned long long dup2(float v) {
    unsigned long long r;
    asm("mov.b64 %0, {%1, %1};" : "=l"(r) : "f"(v));
    return r;
}
__device__ __forceinline__ unsigned long long fma2(unsigned long long a,
                                                   unsigned long long b,
                                                   unsigned long long c) {
    unsigned long long d;
    asm("fma.rn.f32x2 %0, %1, %2, %3;" : "=l"(d) : "l"(a), "l"(b), "l"(c));
    return d;
}
__device__ __forceinline__ void unpk2(unsigned long long v, float& lo, float& hi) {
    asm("mov.b64 {%0, %1}, %2;" : "=f"(lo), "=f"(hi) : "l"(v));
}

// ---------------------------------------------------------------------------
// Kernel 1: per-voxel features -> g_feats (coalesced), id <-> pixel links.
// One warp per voxel; lane handles channels {lane, lane+32} as an f32x2 pair.
// Fold constants computed once per block (warp 0 -> smem, amortized over 8
// warps). Inner loop: float4 L1-hit load + 4 FFMA2 + 2 FMNMX per point.
// ReLU hoisted out of the loop (monotone, commutes with max).
// ---------------------------------------------------------------------------
__global__ void __launch_bounds__(256)
compute_feats_kernel(const float* __restrict__ voxels,
                     const int*   __restrict__ num_points,
                     const int*   __restrict__ coors,
                     const float* __restrict__ W,
                     const float* __restrict__ gamma,
                     const float* __restrict__ beta,
                     const float* __restrict__ rmean,
                     const float* __restrict__ rvar)
{
    // rows: 0:A 1:B 2:C 3:D 4:bb 5..9: sw4..sw8 (paired channels c, c+32)
    __shared__ float2 fold_s[10 * 32];

    const int lane = threadIdx.x & 31;

    if (threadIdx.x < 32) {
        const int t = threadIdx.x;
        const int c0 = t, c1 = t + 32;
        const float s0 = rsqrtf(rvar[c0] + BN_EPS) * gamma[c0];
        const float s1 = rsqrtf(rvar[c1] + BN_EPS) * gamma[c1];
        const float bb0 = beta[c0] - rmean[c0] * s0;
        const float bb1 = beta[c1] - rmean[c1] * s1;
        float sw0[9], sw1[9];
        #pragma unroll
        for (int i = 0; i < 9; i++) {
            sw0[i] = W[i * C_OUT + c0] * s0;
            sw1[i] = W[i * C_OUT + c1] * s1;
        }
        fold_s[0 * 32 + t] = make_float2(sw0[0] + sw0[4] + sw0[7],
                                         sw1[0] + sw1[4] + sw1[7]);   // A
        fold_s[1 * 32 + t] = make_float2(sw0[1] + sw0[5] + sw0[8],
                                         sw1[1] + sw1[5] + sw1[8]);   // B
        fold_s[2 * 32 + t] = make_float2(sw0[2] + sw0[6],
                                         sw1[2] + sw1[6]);            // C
        fold_s[3 * 32 + t] = make_float2(sw0[3], sw1[3]);             // D
        fold_s[4 * 32 + t] = make_float2(bb0, bb1);                   // bb
        #pragma unroll
        for (int i = 0; i < 5; i++)
            fold_s[(5 + i) * 32 + t] = make_float2(sw0[4 + i], sw1[4 + i]);
    }
    __syncthreads();

    const int v = blockIdx.x * (blockDim.x >> 5) + (threadIdx.x >> 5);
    if (v >= V_NUM) return;

    const float4* __restrict__ vox =
        reinterpret_cast<const float4*>(voxels) + (size_t)v * P_NUM;

    int npv = num_points[v];
    npv = npv < 0 ? 0 : (npv > P_NUM ? P_NUM : npv);

    // mean over valid points via warp reduction
    float sx = 0.f, sy = 0.f, sz = 0.f;
    if (lane < npv) {
        float4 pt = vox[lane];
        sx = pt.x; sy = pt.y; sz = pt.z;
    }
    #pragma unroll
    for (int o = 16; o; o >>= 1) {
        sx += __shfl_xor_sync(0xffffffffu, sx, o);
        sy += __shfl_xor_sync(0xffffffffu, sy, o);
        sz += __shfl_xor_sync(0xffffffffu, sz, o);
    }
    const float inv_n = 1.0f / (float)(npv > 1 ? npv : 1);
    const float mx = sx * inv_n, my = sy * inv_n, mz = sz * inv_n;

    const int b  = coors[v * 4 + 0];
    const int yy = coors[v * 4 + 2];
    const int xx = coors[v * 4 + 3];
    const float cx = (float)xx * kVX + kXOFF;
    const float cy = (float)yy * kVX + kXOFF;

    // packed fold constants (LDS.64 into register pairs)
    const unsigned long long* F =
        reinterpret_cast<const unsigned long long*>(fold_s);
    const unsigned long long A2  = F[0 * 32 + lane];
    const unsigned long long B2  = F[1 * 32 + lane];
    const unsigned long long C2  = F[2 * 32 + lane];
    const unsigned long long D2  = F[3 * 32 + lane];
    const unsigned long long bb2 = F[4 * 32 + lane];
    const unsigned long long s42 = F[5 * 32 + lane];
    const unsigned long long s52 = F[6 * 32 + lane];
    const unsigned long long s62 = F[7 * 32 + lane];
    const unsigned long long s72 = F[8 * 32 + lane];
    const unsigned long long s82 = F[9 * 32 + lane];

    // E2 = bb2 - (mx*s4 + my*s5 + mz*s6 + cx*s7 + cy*s8)   (packed)
    unsigned long long E2 = fma2(dup2(-mx), s42, bb2);
    E2 = fma2(dup2(-my), s52, E2);
    E2 = fma2(dup2(-mz), s62, E2);
    E2 = fma2(dup2(-cx), s72, E2);
    E2 = fma2(dup2(-cy), s82, E2);

    float bb0, bb1;
    unpk2(bb2, bb0, bb1);

    // relu hoisted: track pre-relu max; masked points contribute bb.
    float m0 = (npv < P_NUM) ? bb0 : -3.4e38f;
    float m1 = (npv < P_NUM) ? bb1 : -3.4e38f;

    for (int p = 0; p < npv; p++) {
        const float4 pt = vox[p];          // L1 hit (warp-broadcast)
        unsigned long long h = fma2(dup2(pt.x), A2, E2);
        h = fma2(dup2(pt.y), B2, h);
        h = fma2(dup2(pt.z), C2, h);
        h = fma2(dup2(pt.w), D2, h);
        float h0, h1;
        unpk2(h, h0, h1);
        m0 = fmaxf(m0, h0);
        m1 = fmaxf(m1, h1);
    }

    g_feats[(size_t)v * C_OUT + lane]      = fmaxf(m0, 0.0f);
    g_feats[(size_t)v * C_OUT + lane + 32] = fmaxf(m1, 0.0f);
    if (lane == 0) {
        const int pix = b * (NY * NX) + yy * NX + xx;
        g_map[pix] = v;
        g_pix[v]   = pix;
    }
}

// ---------------------------------------------------------------------------
// Kernel 2: coalesced render of canvas + occ (proven shape, ~80us / 61% DRAM).
// Block = 256 threads, owns 128 pixels of one (b,y) row, all 64 channels.
// ---------------------------------------------------------------------------
__global__ void __launch_bounds__(256)
render_kernel(float* __restrict__ out)
{
    __shared__ int map_s[128];

    const int b  = blockIdx.z;
    const int y  = blockIdx.y;
    const int x0 = blockIdx.x * 128;
    const int t  = threadIdx.x;

    const int pix_base = b * (NY * NX) + y * NX + x0;
    if (t < 128) {
        const int pix = pix_base + t;
        int v = g_map[pix];
        if (g_pix[v] != pix) v = -1;   // stale / zero-init -> invalid
        map_s[t] = v;
    }
    __syncthreads();

    const int xq  = (t & 31) * 4;
    const int row = t >> 5;            // 0..7

    const int v0 = map_s[xq + 0];
    const int v1 = map_s[xq + 1];
    const int v2 = map_s[xq + 2];
    const int v3 = map_s[xq + 3];

    const size_t out_xbase = (size_t)y * NX + x0 + xq;

    #pragma unroll
    for (int k = 0; k < 8; k++) {
        const int c = row + k * 8;
        float4 val = make_float4(0.f, 0.f, 0.f, 0.f);
        if (v0 >= 0) val.x = g_feats[(size_t)v0 * C_OUT + c];
        if (v1 >= 0) val.y = g_feats[(size_t)v1 * C_OUT + c];
        if (v2 >= 0) val.z = g_feats[(size_t)v2 * C_OUT + c];
        if (v3 >= 0) val.w = g_feats[(size_t)v3 * C_OUT + c];
        float4* dst = reinterpret_cast<float4*>(
            out + ((size_t)(b * C_OUT + c)) * PLANE + out_xbase);
        __stcs(dst, val);              // streaming: keep feats/map in L2
    }

    if (t < 32) {
        float4 occ = make_float4(v0 >= 0 ? 1.f : 0.f,
                                 v1 >= 0 ? 1.f : 0.f,
                                 v2 >= 0 ? 1.f : 0.f,
                                 v3 >= 0 ? 1.f : 0.f);
        float4* dst = reinterpret_cast<float4*>(
            out + CANVAS + (size_t)b * PLANE + out_xbase);
        __stcs(dst, occ);
    }
}

extern "C" void kernel_launch(void* const* d_in, const int* in_sizes, int n_in,
                              void* d_out, int out_size)
{
    const float* voxels     = (const float*)d_in[0];
    const int*   num_points = (const int*)  d_in[1];
    const int*   coors      = (const int*)  d_in[2];
    const float* W          = (const float*)d_in[3];
    const float* gamma      = (const float*)d_in[4];
    const float* beta       = (const float*)d_in[5];
    const float* rmean      = (const float*)d_in[6];
    const float* rvar       = (const float*)d_in[7];
    float* out = (float*)d_out;

    compute_feats_kernel<<<(V_NUM + 7) / 8, 256>>>(voxels, num_points, coors,
                                                   W, gamma, beta, rmean, rvar);

    dim3 grid(NX / 128, NY, B_NUM);
    render_kernel<<<grid, 256>>>(out);
}

// round 9
// speedup vs baseline: 1.0752x; 1.0118x over previous
#include <cuda_runtime.h>
#include <cstdint>

#define V_NUM 80000
#define P_NUM 20
#define C_OUT 64
#define NY 640
#define NX 640
#define B_NUM 4

static constexpr float BN_EPS = 0.001f;
static constexpr size_t PLANE  = (size_t)NY * NX;                 // 409600
static constexpr size_t CANVAS = (size_t)B_NUM * C_OUT * PLANE;   // 104857600
static constexpr int    MAP_N  = B_NUM * NY * NX;                 // 1638400

__device__ __constant__ float kVX   = 100.0f / 640.0f;
__device__ __constant__ float kXOFF = 100.0f / 640.0f * 0.5f - 50.0f;

// Scratch. g_map / g_pix are zero-initialized at module load; the
// self-validation scheme (g_pix[g_map[pix]] == pix) makes per-call clearing
// unnecessary.
__device__ float g_feats[(size_t)V_NUM * C_OUT];   // 20.5 MB
__device__ int   g_map[MAP_N];                     // pixel -> voxel id
__device__ int   g_pix[V_NUM];                     // voxel id -> pixel

// ---- packed f32x2 helpers --------------------------------------------------
__device__ __forceinline__ unsigned long long dup2(float v) {
    unsigned long long r;
    asm("mov.b64 %0, {%1, %1};" : "=l"(r) : "f"(v));
    return r;
}
__device__ __forceinline__ unsigned long long fma2(unsigned long long a,
                                                   unsigned long long b,
                                                   unsigned long long c) {
    unsigned long long d;
    asm("fma.rn.f32x2 %0, %1, %2, %3;" : "=l"(d) : "l"(a), "l"(b), "l"(c));
    return d;
}
__device__ __forceinline__ unsigned long long mul2(unsigned long long a,
                                                   unsigned long long b) {
    unsigned long long d;
    asm("mul.rn.f32x2 %0, %1, %2;" : "=l"(d) : "l"(a), "l"(b));
    return d;
}
__device__ __forceinline__ void unpk2(unsigned long long v, float& lo, float& hi) {
    asm("mov.b64 {%0, %1}, %2;" : "=f"(lo), "=f"(hi) : "l"(v));
}

// ---------------------------------------------------------------------------
// Kernel 1: per-voxel features. One warp per voxel; lane owns channels
// {lane, lane+32} packed as f32x2.
// Key latency trick: max_p(dot_p + E) = max_p(dot_p) + E, so the point loop
// (dots only) overlaps the mean shuffle-reduction + E chain instead of
// serializing behind them. All DRAM loads front-batched before the fold
// barrier.
// ---------------------------------------------------------------------------
__global__ void __launch_bounds__(256)
compute_feats_kernel(const float* __restrict__ voxels,
                     const int*   __restrict__ num_points,
                     const int4*  __restrict__ coors4,
                     const float* __restrict__ W,
                     const float* __restrict__ gamma,
                     const float* __restrict__ beta,
                     const float* __restrict__ rmean,
                     const float* __restrict__ rvar)
{
    // rows: 0:A 1:B 2:C 3:D 4:bb 5..9: sw4..sw8 (paired channels c, c+32)
    __shared__ float2 fold_s[10 * 32];

    const int lane = threadIdx.x & 31;
    const int v = blockIdx.x * (blockDim.x >> 5) + (threadIdx.x >> 5);
    const int vc = v < V_NUM ? v : V_NUM - 1;      // clamp; real exit later

    // ---- front-batched per-warp DRAM loads (issue before the barrier) ----
    const float4* __restrict__ vox =
        reinterpret_cast<const float4*>(voxels) + (size_t)vc * P_NUM;
    const int   npv_raw = num_points[vc];
    const int4  cr      = coors4[vc];
    float4 myp = make_float4(0.f, 0.f, 0.f, 0.f);
    if (lane < P_NUM) myp = vox[lane];

    // ---- per-block fold (warp 0) ----
    if (threadIdx.x < 32) {
        const int t = threadIdx.x;
        const int c0 = t, c1 = t + 32;
        const float s0 = rsqrtf(rvar[c0] + BN_EPS) * gamma[c0];
        const float s1 = rsqrtf(rvar[c1] + BN_EPS) * gamma[c1];
        const float bb0 = beta[c0] - rmean[c0] * s0;
        const float bb1 = beta[c1] - rmean[c1] * s1;
        float sw0[9], sw1[9];
        #pragma unroll
        for (int i = 0; i < 9; i++) {
            sw0[i] = W[i * C_OUT + c0] * s0;
            sw1[i] = W[i * C_OUT + c1] * s1;
        }
        fold_s[0 * 32 + t] = make_float2(sw0[0] + sw0[4] + sw0[7],
                                         sw1[0] + sw1[4] + sw1[7]);   // A
        fold_s[1 * 32 + t] = make_float2(sw0[1] + sw0[5] + sw0[8],
                                         sw1[1] + sw1[5] + sw1[8]);   // B
        fold_s[2 * 32 + t] = make_float2(sw0[2] + sw0[6],
                                         sw1[2] + sw1[6]);            // C
        fold_s[3 * 32 + t] = make_float2(sw0[3], sw1[3]);             // D
        fold_s[4 * 32 + t] = make_float2(bb0, bb1);                   // bb
        #pragma unroll
        for (int i = 0; i < 5; i++)
            fold_s[(5 + i) * 32 + t] = make_float2(sw0[4 + i], sw1[4 + i]);
    }
    __syncthreads();
    if (v >= V_NUM) return;

    int npv = npv_raw;
    npv = npv < 0 ? 0 : (npv > P_NUM ? P_NUM : npv);

    const unsigned long long* F =
        reinterpret_cast<const unsigned long long*>(fold_s);
    const unsigned long long A2  = F[0 * 32 + lane];
    const unsigned long long B2  = F[1 * 32 + lane];
    const unsigned long long C2  = F[2 * 32 + lane];
    const unsigned long long D2  = F[3 * 32 + lane];
    const unsigned long long bb2 = F[4 * 32 + lane];

    // ---- point loop: dots only, independent of mean/E; 2 accumulators ----
    float ma0 = -3.4e38f, mb0 = -3.4e38f;
    float ma1 = -3.4e38f, mb1 = -3.4e38f;
    int p = 0;
    for (; p + 1 < npv; p += 2) {
        const float4 q0 = vox[p];
        const float4 q1 = vox[p + 1];
        unsigned long long d0 = mul2(dup2(q0.w), D2);
        unsigned long long d1 = mul2(dup2(q1.w), D2);
        d0 = fma2(dup2(q0.z), C2, d0);   d1 = fma2(dup2(q1.z), C2, d1);
        d0 = fma2(dup2(q0.y), B2, d0);   d1 = fma2(dup2(q1.y), B2, d1);
        d0 = fma2(dup2(q0.x), A2, d0);   d1 = fma2(dup2(q1.x), A2, d1);
        float l0, h0, l1, h1;
        unpk2(d0, l0, h0);  unpk2(d1, l1, h1);
        ma0 = fmaxf(ma0, l0);  mb0 = fmaxf(mb0, l1);
        ma1 = fmaxf(ma1, h0);  mb1 = fmaxf(mb1, h1);
    }
    if (p < npv) {
        const float4 q0 = vox[p];
        unsigned long long d0 = mul2(dup2(q0.w), D2);
        d0 = fma2(dup2(q0.z), C2, d0);
        d0 = fma2(dup2(q0.y), B2, d0);
        d0 = fma2(dup2(q0.x), A2, d0);
        float l0, h0;
        unpk2(d0, l0, h0);
        ma0 = fmaxf(ma0, l0);
        ma1 = fmaxf(ma1, h0);
    }
    const float md0 = fmaxf(ma0, mb0);
    const float md1 = fmaxf(ma1, mb1);

    // ---- mean reduction (overlaps the loop above in the scheduler) ----
    float sx = 0.f, sy = 0.f, sz = 0.f;
    if (lane < npv) { sx = myp.x; sy = myp.y; sz = myp.z; }
    #pragma unroll
    for (int o = 16; o; o >>= 1) {
        sx += __shfl_xor_sync(0xffffffffu, sx, o);
        sy += __shfl_xor_sync(0xffffffffu, sy, o);
        sz += __shfl_xor_sync(0xffffffffu, sz, o);
    }
    const float inv_n = 1.0f / (float)(npv > 1 ? npv : 1);
    const float mx = sx * inv_n, my = sy * inv_n, mz = sz * inv_n;

    const float cx = (float)cr.w * kVX + kXOFF;
    const float cy = (float)cr.z * kVX + kXOFF;

    // E2 = bb2 - (mx*s4 + my*s5 + mz*s6 + cx*s7 + cy*s8)
    unsigned long long E2 = fma2(dup2(-mx), F[5 * 32 + lane], bb2);
    E2 = fma2(dup2(-my), F[6 * 32 + lane], E2);
    E2 = fma2(dup2(-mz), F[7 * 32 + lane], E2);
    E2 = fma2(dup2(-cx), F[8 * 32 + lane], E2);
    E2 = fma2(dup2(-cy), F[9 * 32 + lane], E2);
    float E0, E1, bb0, bb1;
    unpk2(E2, E0, E1);
    unpk2(bb2, bb0, bb1);

    // combine: shift dot-max by E; masked (zero-feature) points supply bb.
    float m0 = md0 + E0;
    float m1 = md1 + E1;
    if (npv < P_NUM) { m0 = fmaxf(m0, bb0); m1 = fmaxf(m1, bb1); }

    g_feats[(size_t)v * C_OUT + lane]      = fmaxf(m0, 0.0f);
    g_feats[(size_t)v * C_OUT + lane + 32] = fmaxf(m1, 0.0f);
    if (lane == 0) {
        const int pix = cr.x * (NY * NX) + cr.z * NX + cr.w;
        g_map[pix] = v;
        g_pix[v]   = pix;
    }
}

// ---------------------------------------------------------------------------
// Kernel 2: coalesced render of canvas + occ (proven shape, ~80us / 62% DRAM).
// Block = 256 threads, owns 128 pixels of one (b,y) row, all 64 channels.
// ---------------------------------------------------------------------------
__global__ void __launch_bounds__(256)
render_kernel(float* __restrict__ out)
{
    __shared__ int map_s[128];

    const int b  = blockIdx.z;
    const int y  = blockIdx.y;
    const int x0 = blockIdx.x * 128;
    const int t  = threadIdx.x;

    const int pix_base = b * (NY * NX) + y * NX + x0;
    if (t < 128) {
        const int pix = pix_base + t;
        int v = g_map[pix];
        if (g_pix[v] != pix) v = -1;   // stale / zero-init -> invalid
        map_s[t] = v;
    }
    __syncthreads();

    const int xq  = (t & 31) * 4;
    const int row = t >> 5;            // 0..7

    const int v0 = map_s[xq + 0];
    const int v1 = map_s[xq + 1];
    const int v2 = map_s[xq + 2];
    const int v3 = map_s[xq + 3];

    const size_t out_xbase = (size_t)y * NX + x0 + xq;

    #pragma unroll
    for (int k = 0; k < 8; k++) {
        const int c = row + k * 8;
        float4 val = make_float4(0.f, 0.f, 0.f, 0.f);
        if (v0 >= 0) val.x = g_feats[(size_t)v0 * C_OUT + c];
        if (v1 >= 0) val.y = g_feats[(size_t)v1 * C_OUT + c];
        if (v2 >= 0) val.z = g_feats[(size_t)v2 * C_OUT + c];
        if (v3 >= 0) val.w = g_feats[(size_t)v3 * C_OUT + c];
        float4* dst = reinterpret_cast<float4*>(
            out + ((size_t)(b * C_OUT + c)) * PLANE + out_xbase);
        __stcs(dst, val);              // streaming: keep feats/map in L2
    }

    if (t < 32) {
        float4 occ = make_float4(v0 >= 0 ? 1.f : 0.f,
                                 v1 >= 0 ? 1.f : 0.f,
                                 v2 >= 0 ? 1.f : 0.f,
                                 v3 >= 0 ? 1.f : 0.f);
        float4* dst = reinterpret_cast<float4*>(
            out + CANVAS + (size_t)b * PLANE + out_xbase);
        __stcs(dst, occ);
    }
}

extern "C" void kernel_launch(void* const* d_in, const int* in_sizes, int n_in,
                              void* d_out, int out_size)
{
    const float* voxels     = (const float*)d_in[0];
    const int*   num_points = (const int*)  d_in[1];
    const int4*  coors4     = (const int4*) d_in[2];
    const float* W          = (const float*)d_in[3];
    const float* gamma      = (const float*)d_in[4];
    const float* beta       = (const float*)d_in[5];
    const float* rmean      = (const float*)d_in[6];
    const float* rvar       = (const float*)d_in[7];
    float* out = (float*)d_out;

    compute_feats_kernel<<<(V_NUM + 7) / 8, 256>>>(voxels, num_points, coors4,
                                                   W, gamma, beta, rmean, rvar);

    dim3 grid(NX / 128, NY, B_NUM);
    render_kernel<<<grid, 256>>>(out);
}